// round 16
// baseline (speedup 1.0000x reference)
#include <cuda_runtime.h>
#include <cstdint>

#define B_    2
#define NH_   8
#define N_    4096
#define D_    64
#define K2_   49
#define V_BYTES 12544      // D*K2*4, 16B multiple
#define V_F4  784
#define THREADS 128
#define ROWS  8            // rows per CTA (8 | 4096 so h constant per CTA)

__device__ __forceinline__ uint32_t smem_u32(const void* p) {
    return (uint32_t)__cvta_generic_to_shared(p);
}
__device__ __forceinline__ void cp16(uint32_t dst, const void* src) {
    asm volatile("cp.async.cg.shared.global [%0], [%1], 16;\n" :: "r"(dst), "l"(src));
}
__device__ __forceinline__ void cp_commit() {
    asm volatile("cp.async.commit_group;\n" ::: "memory");
}
template <int NPend>
__device__ __forceinline__ void cp_wait() {
    asm volatile("cp.async.wait_group %0;\n" :: "n"(NPend) : "memory");
}
__device__ __forceinline__ void mbar_init(uint32_t a, uint32_t cnt) {
    asm volatile("mbarrier.init.shared.b64 [%0], %1;" :: "r"(a), "r"(cnt) : "memory");
}
__device__ __forceinline__ void mbar_expect_tx(uint32_t a, uint32_t bytes) {
    asm volatile("mbarrier.arrive.expect_tx.shared.b64 _, [%0], %1;"
                 :: "r"(a), "r"(bytes) : "memory");
}
__device__ __forceinline__ void bulk_g2s(uint32_t dst, const void* src,
                                         uint32_t bytes, uint32_t mbar) {
    asm volatile(
        "cp.async.bulk.shared::cta.global.mbarrier::complete_tx::bytes "
        "[%0], [%1], %2, [%3];"
        :: "r"(dst), "l"(src), "r"(bytes), "r"(mbar) : "memory");
}
__device__ __forceinline__ void mbar_wait(uint32_t a, uint32_t parity) {
    asm volatile(
        "{\n\t.reg .pred P;\n\t"
        "WL_%=:\n\t"
        "mbarrier.try_wait.parity.acquire.cta.shared::cta.b64 P, [%0], %1, 0x989680;\n\t"
        "@P bra.uni WD_%=;\n\t"
        "bra.uni WL_%=;\n\t"
        "WD_%=:\n\t}"
        :: "r"(a), "r"(parity) : "memory");
}

struct __align__(16) Stage {
    float4 v[V_F4];        // 12544 B  (phase-2 tail for d=63 reads q[0]*0: in-bounds)
    float  q[D_];          // 256 B
};

__global__ __launch_bounds__(THREADS)
void sw_attention_av_pipe2(const float* __restrict__ q_norm,      // [B,NH,N,D]
                           const float* __restrict__ attn_local,  // [B,NH,N,K2]
                           const float* __restrict__ v_local,     // [B,NH,N,D,K2]
                           const float* __restrict__ tokens,      // [NH,D,K2]
                           const float* __restrict__ bias,        // [NH,N,K2]
                           float* __restrict__ out)               // [B,NH,N,D]
{
    __shared__ Stage    st[2];               // 25600 B
    __shared__ uint64_t mbar[2];
    __shared__ float    s_part[2][64];       // d-half partials, indexed by k
    __shared__ float    s_attn[2][K2_ + 1];  // [49] = 0 pad (never rewritten)

    const int t    = threadIdx.x;
    const int warp = t >> 5;
    const int lane = t & 31;
    const int row0 = blockIdx.x * ROWS;
    const int h    = (row0 >> 12) & (NH_ - 1);
    const int n0   = row0 & (N_ - 1);

    const int  kbase  = (warp >> 1) << 5;    // warp -> (k-half, d-half) quadrant
    const int  dhalf  = warp & 1;
    const int  dbase  = dhalf << 5;
    const int  k      = kbase + lane;
    const bool kvalid = (k < K2_);

    float tkr[32];                           // tokens quadrant, loaded once

    if (t == 0) { mbar_init(smem_u32(&mbar[0]), 1); mbar_init(smem_u32(&mbar[1]), 1); }
    if (t < 2)  s_attn[t][K2_] = 0.f;
    __syncthreads();

    auto prefetch_v = [&](int s, int row) {
        if (t == 0) {
            mbar_expect_tx(smem_u32(&mbar[s]), V_BYTES);
            bulk_g2s(smem_u32(st[s].v),
                     reinterpret_cast<const char*>(v_local) + (size_t)row * V_BYTES,
                     V_BYTES, smem_u32(&mbar[s]));
        }
    };
    auto prefetch_q = [&](int s, int row) {
        if (t < D_ / 4)
            cp16(smem_u32(st[s].q) + (uint32_t)t * 16u,
                 reinterpret_cast<const float4*>(q_norm + (size_t)row * D_) + t);
        cp_commit();
    };
    auto phase1a = [&](int rr) {             // all warps; writes s_part
        const float4* q4 = reinterpret_cast<const float4*>(st[rr & 1].q + dbase);
        float p0 = 0.f, p1 = 0.f;
#pragma unroll
        for (int c = 0; c < 8; c++) {
            const float4 qv = q4[c];
            p0 = fmaf(qv.x, tkr[4 * c + 0], p0);
            p1 = fmaf(qv.y, tkr[4 * c + 1], p1);
            p0 = fmaf(qv.z, tkr[4 * c + 2], p0);
            p1 = fmaf(qv.w, tkr[4 * c + 3], p1);
        }
        if (kvalid) s_part[dhalf][k] = p0 + p1;
    };
    auto phase1b = [&](int rr) {             // t < 49; al/bias straight from L2
        if (t < K2_)
            s_attn[rr & 1][t] = s_part[0][t] + s_part[1][t]
                + __ldg(attn_local + (size_t)(row0 + rr) * K2_ + t)
                + __ldg(bias + ((size_t)h * N_ + n0 + rr) * K2_ + t);
    };

    // ---- prologue: both slots streaming immediately
    prefetch_q(0, row0);
    prefetch_q(1, row0 + 1);
    prefetch_v(0, row0);
    prefetch_v(1, row0 + 1);

    {   // tokens -> registers (coalesced; overlaps the copies)
        const float* tokh = tokens + h * (D_ * K2_);
#pragma unroll
        for (int i = 0; i < 32; i++)
            tkr[i] = kvalid ? __ldg(tokh + (dbase + i) * K2_ + k) : 0.f;
    }

    cp_wait<1>();            // q(0) landed (q(1) still outstanding)
    __syncthreads();
    phase1a(0);
    __syncthreads();
    phase1b(0);              // -> s_attn[0]; ordered before phase2(0) by sync A

    // ---- steady loop: 2 barriers per row
    for (int r = 0; r < ROWS; r++) {
        if (r + 2 < ROWS) { prefetch_q(r & 1, row0 + r + 2); cp_wait<1>(); }
        else              cp_wait<0>();
        mbar_wait(smem_u32(&mbar[r & 1]), (uint32_t)((r >> 1) & 1));   // v(r) done
        __syncthreads();     // sync A

        if (r + 1 < ROWS) phase1a(r + 1);

        {   // phase 2: all 128 threads, 2 per d
            const int d     = t >> 1;
            const int start = (t & 1) * 25;
            const float* vd = reinterpret_cast<const float*>(st[r & 1].v) + d * K2_ + start;
            const float* ak = s_attn[r & 1] + start;
            float acc0 = 0.f, acc1 = 0.f;
#pragma unroll
            for (int j = 0; j < 24; j += 2) {
                acc0 = fmaf(ak[j + 0], vd[j + 0], acc0);
                acc1 = fmaf(ak[j + 1], vd[j + 1], acc1);
            }
            acc0 = fmaf(ak[24], vd[24], acc0);       // start=25 -> ak[49]=0 exact
            acc0 += acc1;
            acc0 += __shfl_xor_sync(0xFFFFFFFFu, acc0, 1);
            if (!(t & 1))
                out[(size_t)(row0 + r) * D_ + d] = acc0;
        }

        __syncthreads();     // sync B: slot r&1 v free

        if (r + 2 < ROWS) prefetch_v(r & 1, row0 + r + 2);
        if (r + 1 < ROWS) phase1b(r + 1);
    }
}

extern "C" void kernel_launch(void* const* d_in, const int* in_sizes, int n_in,
                              void* d_out, int out_size)
{
    const float* q_norm     = (const float*)d_in[0];
    const float* attn_local = (const float*)d_in[1];
    const float* v_local    = (const float*)d_in[2];
    const float* tokens     = (const float*)d_in[3];
    const float* bias       = (const float*)d_in[4];
    float* out = (float*)d_out;

    const int blocks = (B_ * NH_ * N_) / ROWS;   // 8192
    sw_attention_av_pipe2<<<blocks, THREADS>>>(q_norm, attn_local, v_local,
                                               tokens, bias, out);
}

// round 17
// speedup vs baseline: 1.0118x; 1.0118x over previous
#include <cuda_runtime.h>
#include <cstdint>

#define B_    2
#define NH_   8
#define N_    4096
#define D_    64
#define K2_   49
#define V_BYTES 12544      // D*K2*4, 16B multiple
#define V_F4  784
#define THREADS 128
#define ROWS  16           // rows per CTA (16 | 4096 so h constant per CTA)

__device__ __forceinline__ uint32_t smem_u32(const void* p) {
    return (uint32_t)__cvta_generic_to_shared(p);
}
__device__ __forceinline__ void cp16(uint32_t dst, const void* src) {
    asm volatile("cp.async.cg.shared.global [%0], [%1], 16;\n" :: "r"(dst), "l"(src));
}
__device__ __forceinline__ void cp4(uint32_t dst, const void* src) {
    asm volatile("cp.async.ca.shared.global [%0], [%1], 4;\n" :: "r"(dst), "l"(src));
}
__device__ __forceinline__ void cp_commit() {
    asm volatile("cp.async.commit_group;\n" ::: "memory");
}
template <int NPend>
__device__ __forceinline__ void cp_wait() {
    asm volatile("cp.async.wait_group %0;\n" :: "n"(NPend) : "memory");
}
__device__ __forceinline__ void mbar_init(uint32_t a, uint32_t cnt) {
    asm volatile("mbarrier.init.shared.b64 [%0], %1;" :: "r"(a), "r"(cnt) : "memory");
}
__device__ __forceinline__ void mbar_expect_tx(uint32_t a, uint32_t bytes) {
    asm volatile("mbarrier.arrive.expect_tx.shared.b64 _, [%0], %1;"
                 :: "r"(a), "r"(bytes) : "memory");
}
__device__ __forceinline__ void bulk_g2s(uint32_t dst, const void* src,
                                         uint32_t bytes, uint32_t mbar) {
    asm volatile(
        "cp.async.bulk.shared::cta.global.mbarrier::complete_tx::bytes "
        "[%0], [%1], %2, [%3];"
        :: "r"(dst), "l"(src), "r"(bytes), "r"(mbar) : "memory");
}
__device__ __forceinline__ void mbar_wait(uint32_t a, uint32_t parity) {
    asm volatile(
        "{\n\t.reg .pred P;\n\t"
        "WL_%=:\n\t"
        "mbarrier.try_wait.parity.acquire.cta.shared::cta.b64 P, [%0], %1, 0x989680;\n\t"
        "@P bra.uni WD_%=;\n\t"
        "bra.uni WL_%=;\n\t"
        "WD_%=:\n\t}"
        :: "r"(a), "r"(parity) : "memory");
}

struct __align__(16) Stage {
    float4 v[V_F4];        // 12544 B
    float  q[D_];          // 256 B
    float  al[K2_];        // 196 B
    float  b[K2_];         // 196 B
    float  pad[2];         // sizeof = 13200
};

__global__ __launch_bounds__(THREADS)
void sw_attention_av_bulk16(const float* __restrict__ q_norm,      // [B,NH,N,D]
                            const float* __restrict__ attn_local,  // [B,NH,N,K2]
                            const float* __restrict__ v_local,     // [B,NH,N,D,K2]
                            const float* __restrict__ tokens,      // [NH,D,K2]
                            const float* __restrict__ bias,        // [NH,N,K2]
                            float* __restrict__ out)               // [B,NH,N,D]
{
    __shared__ Stage    st[2];           // 26400 B
    __shared__ uint64_t mbar[2];
    __shared__ float    s_part[2][64];   // d-half partials, indexed by k
    __shared__ float    s_attn[K2_];

    const int t    = threadIdx.x;
    const int warp = t >> 5;
    const int lane = t & 31;
    const int row0 = blockIdx.x * ROWS;
    const int h    = (row0 >> 12) & (NH_ - 1);

    // warp -> (k-half, d-half) quadrant for phase 1
    const int  kbase  = (warp >> 1) << 5;
    const int  dhalf  = warp & 1;
    const int  dbase  = dhalf << 5;
    const int  k      = kbase + lane;
    const bool kvalid = (k < K2_);

    if (t == 0) { mbar_init(smem_u32(&mbar[0]), 1); mbar_init(smem_u32(&mbar[1]), 1); }
    __syncthreads();

    // v tile: single bulk copy per row, issued by thread 0 (off the LSU path)
    auto prefetch_v = [&](int s, int row) {
        if (t == 0) {
            mbar_expect_tx(smem_u32(&mbar[s]), V_BYTES);
            bulk_g2s(smem_u32(st[s].v),
                     reinterpret_cast<const char*>(v_local) + (size_t)row * V_BYTES,
                     V_BYTES, smem_u32(&mbar[s]));
        }
    };
    // small operands (q / attn_local / bias) via cp.async group
    auto prefetch_small = [&](int s, int row) {
        if (t < D_ / 4)
            cp16(smem_u32(st[s].q) + (uint32_t)t * 16u,
                 reinterpret_cast<const float4*>(q_norm + (size_t)row * D_) + t);
        if (t < K2_) {
            const int n = row & (N_ - 1);
            cp4(smem_u32(st[s].al) + (uint32_t)t * 4u, attn_local + (size_t)row * K2_ + t);
            cp4(smem_u32(st[s].b)  + (uint32_t)t * 4u, bias + ((size_t)h * N_ + n) * K2_ + t);
        }
        cp_commit();
    };

    prefetch_small(0, row0);
    prefetch_v(0, row0);

    // ---- hoist tokens into registers (once per CTA; coalesced)
    float tk[32];
    {
        const float* tokh = tokens + h * (D_ * K2_);
#pragma unroll
        for (int i = 0; i < 32; i++)
            tk[i] = kvalid ? __ldg(tokh + (dbase + i) * K2_ + k) : 0.f;
    }

    for (int r = 0; r < ROWS; r++) {
        if (r + 1 < ROWS) {
            prefetch_small((r + 1) & 1, row0 + r + 1);
            prefetch_v((r + 1) & 1, row0 + r + 1);
            cp_wait<1>();                          // this thread's small group r done
        } else {
            cp_wait<0>();
        }
        mbar_wait(smem_u32(&mbar[r & 1]), (uint32_t)((r >> 1) & 1));  // v tile r done
        __syncthreads();                           // all threads' small slices visible

        const Stage& S = st[r & 1];

        // ---- phase 1a: quadrant partial dot (registers x LDS broadcast)
        {
            const float4* q4 = reinterpret_cast<const float4*>(S.q + dbase);
            float p0 = 0.f, p1 = 0.f;
#pragma unroll
            for (int c = 0; c < 8; c++) {
                const float4 qv = q4[c];
                p0 = fmaf(qv.x, tk[4 * c + 0], p0);
                p1 = fmaf(qv.y, tk[4 * c + 1], p1);
                p0 = fmaf(qv.z, tk[4 * c + 2], p0);
                p1 = fmaf(qv.w, tk[4 * c + 3], p1);
            }
            if (kvalid) s_part[dhalf][k] = p0 + p1;
        }
        __syncthreads();

        // ---- phase 1b: combine halves + bias + attn_local
        if (t < K2_)
            s_attn[t] = s_part[0][t] + s_part[1][t] + S.al[t] + S.b[t];
        __syncthreads();

        // ---- phase 2: out[d] = sum_k attn[k] * v[d,k]  (stride-49: conflict-free)
        if (t < D_) {
            const float* vd = reinterpret_cast<const float*>(S.v) + t * K2_;
            float acc0 = 0.f, acc1 = 0.f;
#pragma unroll
            for (int kk = 0; kk < 48; kk += 2) {
                acc0 = fmaf(s_attn[kk + 0], vd[kk + 0], acc0);
                acc1 = fmaf(s_attn[kk + 1], vd[kk + 1], acc1);
            }
            acc0 = fmaf(s_attn[48], vd[48], acc0);
            out[(size_t)(row0 + r) * D_ + t] = acc0 + acc1;
        }

        __syncthreads();    // readers done -> slot r&1 and its mbar reusable
    }
}

extern "C" void kernel_launch(void* const* d_in, const int* in_sizes, int n_in,
                              void* d_out, int out_size)
{
    const float* q_norm     = (const float*)d_in[0];
    const float* attn_local = (const float*)d_in[1];
    const float* v_local    = (const float*)d_in[2];
    const float* tokens     = (const float*)d_in[3];
    const float* bias       = (const float*)d_in[4];
    float* out = (float*)d_out;

    const int blocks = (B_ * NH_ * N_) / ROWS;   // 4096
    sw_attention_av_bulk16<<<blocks, THREADS>>>(q_norm, attn_local, v_local,
                                                tokens, bias, out);
}